// round 5
// baseline (speedup 1.0000x reference)
#include <cuda_runtime.h>
#include <math.h>

#define HID    256
#define HHALF  128
#define NGRAPH 8192
#define NMAX   1048576
#define CAP    1024

// Scratch (allocation-free rule: __device__ globals)
__device__ float g_gate[NMAX];
__device__ int   g_off[NGRAPH + 1];

__device__ __forceinline__ unsigned f2tf32(float f) {
    unsigned r;
    asm("cvt.rna.tf32.f32 %0, %1;" : "=r"(r) : "f"(f));
    return r;
}

__device__ __forceinline__ void mma_tf32(float* d, const unsigned* a, const unsigned* b) {
    asm volatile(
        "mma.sync.aligned.m16n8k8.row.col.f32.tf32.tf32.f32 "
        "{%0,%1,%2,%3}, {%4,%5,%6,%7}, {%8,%9}, {%0,%1,%2,%3};\n"
        : "+f"(d[0]), "+f"(d[1]), "+f"(d[2]), "+f"(d[3])
        : "r"(a[0]), "r"(a[1]), "r"(a[2]), "r"(a[3]), "r"(b[0]), "r"(b[1]));
}

// smem word layout (dynamic):
//   W1s : [256][136]  tf32 bits of W1 (pad 136 -> conflict-free B frag loads)
//   xs  : [128][36]   tf32 bits of x chunk (pad 36 -> conflict-free A frag loads)
//   b1s : [128], w2s : [128], gpart : [128][2]
#define W1S_STRIDE 136
#define XS_STRIDE  36
#define SMEM_WORDS (HID * W1S_STRIDE + 128 * XS_STRIDE + 128 + 128 + 256)

__global__ __launch_bounds__(256)
void gate_kernel(const float* __restrict__ x, const float* __restrict__ W1,
                 const float* __restrict__ b1v, const float* __restrict__ W2,
                 const float* __restrict__ b2, int N)
{
    extern __shared__ unsigned smemw[];
    unsigned* W1s  = smemw;                          // 256*136
    unsigned* xs   = W1s + HID * W1S_STRIDE;         // 128*36
    float*    b1s  = (float*)(xs + 128 * XS_STRIDE); // 128
    float*    w2s  = b1s + 128;                      // 128
    float*    gpart= w2s + 128;                      // 128*2

    const int tid  = threadIdx.x;
    const int lane = tid & 31;
    const int warp = tid >> 5;
    const int t    = lane & 3;   // threadID_in_group
    const int g    = lane >> 2;  // groupID
    const int mw   = warp & 3;   // 4 warps along M
    const int nw   = warp >> 2;  // 2 warps along N
    const int nb   = blockIdx.x * 128;

    // Stage W1 (as tf32 bits), b1, W2
    for (int idx = tid; idx < HID * HHALF; idx += 256) {
        int k = idx >> 7, j = idx & 127;
        W1s[k * W1S_STRIDE + j] = f2tf32(W1[idx]);
    }
    if (tid < 128) { b1s[tid] = b1v[tid]; w2s[tid] = W2[tid]; }

    float acc[2][8][4];
    #pragma unroll
    for (int mt = 0; mt < 2; mt++)
        #pragma unroll
        for (int nt = 0; nt < 8; nt++)
            #pragma unroll
            for (int i = 0; i < 4; i++) acc[mt][nt][i] = 0.f;

    for (int kc = 0; kc < 8; kc++) {
        __syncthreads();  // previous xs reads done (also covers W1s/b1s on first iter)
        for (int idx = tid; idx < 128 * 32; idx += 256) {
            int r = idx >> 5, c = idx & 31;
            int node = nb + r;
            float v = (node < N) ? x[(size_t)node * HID + kc * 32 + c] : 0.f;
            xs[r * XS_STRIDE + c] = f2tf32(v);
        }
        __syncthreads();

        #pragma unroll
        for (int s = 0; s < 4; s++) {
            const int kl = s * 8;
            unsigned a[2][4];
            #pragma unroll
            for (int mt = 0; mt < 2; mt++) {
                int r0 = mw * 32 + mt * 16 + g;
                a[mt][0] = xs[r0 * XS_STRIDE + kl + t];
                a[mt][1] = xs[(r0 + 8) * XS_STRIDE + kl + t];
                a[mt][2] = xs[r0 * XS_STRIDE + kl + t + 4];
                a[mt][3] = xs[(r0 + 8) * XS_STRIDE + kl + t + 4];
            }
            const int kg = kc * 32 + kl;
            #pragma unroll
            for (int nt = 0; nt < 8; nt++) {
                int cb = nw * 64 + nt * 8 + g;
                unsigned b[2];
                b[0] = W1s[(kg + t) * W1S_STRIDE + cb];
                b[1] = W1s[(kg + t + 4) * W1S_STRIDE + cb];
                mma_tf32(acc[0][nt], a[0], b);
                mma_tf32(acc[1][nt], a[1], b);
            }
        }
    }

    // Epilogue: gate = tanh(pre + b1) . W2 + b2
    const float b2v = b2[0];
    #pragma unroll
    for (int mt = 0; mt < 2; mt++) {
        float s0 = 0.f, s1 = 0.f;
        #pragma unroll
        for (int nt = 0; nt < 8; nt++) {
            int c = nw * 64 + nt * 8 + 2 * t;
            float bc0 = b1s[c], bc1 = b1s[c + 1];
            float wc0 = w2s[c], wc1 = w2s[c + 1];
            s0 += tanhf(acc[mt][nt][0] + bc0) * wc0 + tanhf(acc[mt][nt][1] + bc1) * wc1;
            s1 += tanhf(acc[mt][nt][2] + bc0) * wc0 + tanhf(acc[mt][nt][3] + bc1) * wc1;
        }
        s0 += __shfl_xor_sync(0xffffffffu, s0, 1);
        s0 += __shfl_xor_sync(0xffffffffu, s0, 2);
        s1 += __shfl_xor_sync(0xffffffffu, s1, 1);
        s1 += __shfl_xor_sync(0xffffffffu, s1, 2);
        if (t == 0) {
            int r = mw * 32 + mt * 16 + g;
            gpart[r * 2 + nw]       = s0;
            gpart[(r + 8) * 2 + nw] = s1;
        }
    }
    __syncthreads();
    if (tid < 128) {
        int node = nb + tid;
        if (node < N)
            g_gate[node] = gpart[tid * 2 + 0] + gpart[tid * 2 + 1] + b2v;
    }
}

// Dtype-agnostic batch read. JAX with x64 disabled downcasts int64->int32
// silently; detect at runtime. The batch array is sorted, last value ~8191.
// word[N-1] (int32 view): int32 buffer -> last batch value (>=1);
//                         int64 buffer -> high word of elem (N-1)/2 -> 0.
__device__ __forceinline__ int batch_at(const void* batch, int i, int is64) {
    if (is64) return (int)((const long long*)batch)[i];
    return ((const int*)batch)[i];
}

// Segment boundaries from the sorted batch array: g_off[g] = first index with batch >= g
__global__ void offsets_kernel(const void* __restrict__ batch, int N)
{
    int i = blockIdx.x * blockDim.x + threadIdx.x;
    if (i >= N) return;
    const int is64 = (((const int*)batch)[N - 1] == 0) ? 1 : 0;
    int bc = batch_at(batch, i, is64);
    bc = min(max(bc, 0), NGRAPH - 1);
    int bp;
    if (i == 0) bp = -1;
    else {
        bp = batch_at(batch, i - 1, is64);
        bp = min(max(bp, -1), NGRAPH - 1);
    }
    for (int gg = bp + 1; gg <= bc; gg++) g_off[gg] = i;
    if (i == N - 1)
        for (int gg = bc + 1; gg <= NGRAPH; gg++) g_off[gg] = N;
}

// One block per graph: local max -> exp-sum -> weighted feature sum (no atomics)
__global__ __launch_bounds__(256)
void readout_kernel(const float* __restrict__ x, float* __restrict__ out, int N)
{
    const int gid = blockIdx.x;
    const int tid = threadIdx.x;  // column index (H == 256 == blockDim)
    if (N <= 0) { out[(size_t)gid * HID + tid] = 0.f; return; }
    const int s = g_off[gid], e = g_off[gid + 1];
    if (e <= s) { out[(size_t)gid * HID + tid] = 0.f; return; }

    __shared__ float red[256];
    __shared__ float es[CAP];

    // max
    float mx = -3.0e38f;
    for (int i = s + tid; i < e; i += 256) mx = fmaxf(mx, g_gate[i]);
    red[tid] = mx; __syncthreads();
    for (int o = 128; o > 0; o >>= 1) {
        if (tid < o) red[tid] = fmaxf(red[tid], red[tid + o]);
        __syncthreads();
    }
    mx = red[0];
    __syncthreads();

    // sum of exp
    float sm = 0.f;
    for (int i = s + tid; i < e; i += 256) sm += expf(g_gate[i] - mx);
    red[tid] = sm; __syncthreads();
    for (int o = 128; o > 0; o >>= 1) {
        if (tid < o) red[tid] += red[tid + o];
        __syncthreads();
    }
    const float inv = 1.f / (red[0] + 1e-16f);
    __syncthreads();

    // weighted sum of node features, chunked exp weights in smem
    float a0 = 0.f, a1 = 0.f, a2 = 0.f, a3 = 0.f;
    for (int cs = s; cs < e; cs += CAP) {
        int cn = min(CAP, e - cs);
        for (int i = tid; i < cn; i += 256) es[i] = expf(g_gate[cs + i] - mx);
        __syncthreads();
        const float* xp = x + (size_t)cs * HID + tid;
        int n = 0;
        for (; n + 4 <= cn; n += 4) {
            a0 += es[n]     * xp[0];
            a1 += es[n + 1] * xp[HID];
            a2 += es[n + 2] * xp[2 * HID];
            a3 += es[n + 3] * xp[3 * HID];
            xp += 4 * HID;
        }
        for (; n < cn; n++) { a0 += es[n] * xp[0]; xp += HID; }
        __syncthreads();
    }
    out[(size_t)gid * HID + tid] = (a0 + a1 + a2 + a3) * inv;
}

extern "C" void kernel_launch(void* const* d_in, const int* in_sizes, int n_in,
                              void* d_out, int out_size)
{
    const float* x     = (const float*)d_in[0];
    const float* W1    = (const float*)d_in[1];
    const float* b1    = (const float*)d_in[2];
    const float* W2    = (const float*)d_in[3];
    const float* b2    = (const float*)d_in[4];
    const void*  batch = d_in[5];
    float* out = (float*)d_out;
    const int N = in_sizes[5];

    (void)n_in; (void)out_size;

    cudaFuncSetAttribute(gate_kernel,
                         cudaFuncAttributeMaxDynamicSharedMemorySize,
                         SMEM_WORDS * 4);

    if (N > 0) {
        int gblocks = (N + 127) / 128;
        gate_kernel<<<gblocks, 256, SMEM_WORDS * 4>>>(x, W1, b1, W2, b2, N);
        offsets_kernel<<<(N + 255) / 256, 256>>>(batch, N);
    }
    readout_kernel<<<NGRAPH, 256>>>(x, out, N);
}

// round 7
// speedup vs baseline: 3.1746x; 3.1746x over previous
#include <cuda_runtime.h>
#include <math.h>

#define HID    256
#define HHALF  128
#define NGRAPH 8192
#define NMAX   1048576
#define CAP    1024
#define NSM    148

// Scratch (allocation-free rule: __device__ globals)
__device__ float g_gate[NMAX];
__device__ int   g_off[NGRAPH + 1];

__device__ __forceinline__ unsigned f2tf32(float f) {
    unsigned r;
    asm("cvt.rna.tf32.f32 %0, %1;" : "=r"(r) : "f"(f));
    return r;
}

__device__ __forceinline__ float tanh_fast(float v) {
    float r;
    asm("tanh.approx.f32 %0, %1;" : "=f"(r) : "f"(v));
    return r;
}

__device__ __forceinline__ void mma_tf32(float* d, const unsigned* a, const unsigned* b) {
    asm volatile(
        "mma.sync.aligned.m16n8k8.row.col.f32.tf32.tf32.f32 "
        "{%0,%1,%2,%3}, {%4,%5,%6,%7}, {%8,%9}, {%0,%1,%2,%3};\n"
        : "+f"(d[0]), "+f"(d[1]), "+f"(d[2]), "+f"(d[3])
        : "r"(a[0]), "r"(a[1]), "r"(a[2]), "r"(a[3]), "r"(b[0]), "r"(b[1]));
}

// smem word layout (dynamic):
//   W1s : [256][136]   tf32 bits of W1 (pad 136 -> conflict-free B frag loads)
//   xs  : 2 x [128][36] raw fp32 bits of x chunk, double-buffered for cp.async
//   b1s : [128], w2s : [128], gpart : [128][2]
#define W1S_STRIDE 136
#define XS_STRIDE  36
#define XS_WORDS   (128 * XS_STRIDE)
#define SMEM_WORDS (HID * W1S_STRIDE + 2 * XS_WORDS + 128 + 128 + 256)

// Stage one 128x32 chunk of x into xs via cp.async (16B chunks, zero-fill tail rows)
__device__ __forceinline__ void stage_x(unsigned* xsbuf, const float* __restrict__ x,
                                        int nb, int kc, int N, int tid)
{
    #pragma unroll
    for (int j = 0; j < 4; j++) {
        int idx = tid + j * 256;          // 0..1023
        int r   = idx >> 3;               // row 0..127
        int cw  = (idx & 7) * 4;          // word col 0..28
        int node = nb + r;
        int ok = (node < N);
        const float* src = x + (size_t)(ok ? node : 0) * HID + kc * 32 + cw;
        unsigned daddr = (unsigned)__cvta_generic_to_shared(xsbuf + r * XS_STRIDE + cw);
        int sz = ok ? 16 : 0;
        asm volatile("cp.async.cg.shared.global [%0], [%1], 16, %2;\n"
                     :: "r"(daddr), "l"(src), "r"(sz));
    }
    asm volatile("cp.async.commit_group;\n");
}

__global__ __launch_bounds__(256)
void gate_kernel(const float* __restrict__ x, const float* __restrict__ W1,
                 const float* __restrict__ b1v, const float* __restrict__ W2,
                 const float* __restrict__ b2, int N, int ntiles)
{
    extern __shared__ unsigned smemw[];
    unsigned* W1s   = smemw;                           // 256*136
    unsigned* xs0   = W1s + HID * W1S_STRIDE;          // 128*36
    unsigned* xs1   = xs0 + XS_WORDS;                  // 128*36
    float*    b1s   = (float*)(xs1 + XS_WORDS);        // 128
    float*    w2s   = b1s + 128;                       // 128
    float*    gpart = w2s + 128;                       // 128*2

    const int tid  = threadIdx.x;
    const int lane = tid & 31;
    const int warp = tid >> 5;
    const int t    = lane & 3;   // threadID_in_group
    const int g    = lane >> 2;  // groupID
    const int mw   = warp & 3;   // 4 warps along M
    const int nw   = warp >> 2;  // 2 warps along N

    // Stage W1 (tf32 bits), b1, W2 — ONCE per persistent CTA
    for (int idx = tid; idx < HID * HHALF; idx += 256) {
        int k = idx >> 7, j = idx & 127;
        W1s[k * W1S_STRIDE + j] = f2tf32(W1[idx]);
    }
    if (tid < 128) { b1s[tid] = b1v[tid]; w2s[tid] = W2[tid]; }
    const float b2v = b2[0];
    __syncthreads();

    unsigned* bufs[2] = {xs0, xs1};

    for (int tile = blockIdx.x; tile < ntiles; tile += gridDim.x) {
        const int nb = tile * 128;

        float acc[2][8][4];
        #pragma unroll
        for (int mt = 0; mt < 2; mt++)
            #pragma unroll
            for (int nt = 0; nt < 8; nt++)
                #pragma unroll
                for (int i = 0; i < 4; i++) acc[mt][nt][i] = 0.f;

        // pipeline prologue
        stage_x(bufs[0], x, nb, 0, N, tid);

        for (int kc = 0; kc < 8; kc++) {
            if (kc < 7) {
                stage_x(bufs[(kc + 1) & 1], x, nb, kc + 1, N, tid);
                asm volatile("cp.async.wait_group 1;\n");
            } else {
                asm volatile("cp.async.wait_group 0;\n");
            }
            __syncthreads();

            const unsigned* xsb = bufs[kc & 1];
            #pragma unroll
            for (int s = 0; s < 4; s++) {
                const int kl = s * 8;
                unsigned a[2][4];
                #pragma unroll
                for (int mt = 0; mt < 2; mt++) {
                    int r0 = mw * 32 + mt * 16 + g;
                    a[mt][0] = xsb[r0 * XS_STRIDE + kl + t];
                    a[mt][1] = xsb[(r0 + 8) * XS_STRIDE + kl + t];
                    a[mt][2] = xsb[r0 * XS_STRIDE + kl + t + 4];
                    a[mt][3] = xsb[(r0 + 8) * XS_STRIDE + kl + t + 4];
                }
                const int kg = kc * 32 + kl;
                #pragma unroll
                for (int nt = 0; nt < 8; nt++) {
                    int cb = nw * 64 + nt * 8 + g;
                    unsigned b[2];
                    b[0] = W1s[(kg + t) * W1S_STRIDE + cb];
                    b[1] = W1s[(kg + t + 4) * W1S_STRIDE + cb];
                    mma_tf32(acc[0][nt], a[0], b);
                    mma_tf32(acc[1][nt], a[1], b);
                }
            }
            __syncthreads();  // compute done before this buffer is re-staged
        }

        // Epilogue: gate = tanh(pre + b1) . W2 + b2
        #pragma unroll
        for (int mt = 0; mt < 2; mt++) {
            float s0 = 0.f, s1 = 0.f;
            #pragma unroll
            for (int nt = 0; nt < 8; nt++) {
                int c = nw * 64 + nt * 8 + 2 * t;
                float bc0 = b1s[c], bc1 = b1s[c + 1];
                float wc0 = w2s[c], wc1 = w2s[c + 1];
                s0 += tanh_fast(acc[mt][nt][0] + bc0) * wc0 + tanh_fast(acc[mt][nt][1] + bc1) * wc1;
                s1 += tanh_fast(acc[mt][nt][2] + bc0) * wc0 + tanh_fast(acc[mt][nt][3] + bc1) * wc1;
            }
            s0 += __shfl_xor_sync(0xffffffffu, s0, 1);
            s0 += __shfl_xor_sync(0xffffffffu, s0, 2);
            s1 += __shfl_xor_sync(0xffffffffu, s1, 1);
            s1 += __shfl_xor_sync(0xffffffffu, s1, 2);
            if (t == 0) {
                int r = mw * 32 + mt * 16 + g;
                gpart[r * 2 + nw]       = s0;
                gpart[(r + 8) * 2 + nw] = s1;
            }
        }
        __syncthreads();
        if (tid < 128) {
            int node = nb + tid;
            if (node < N)
                g_gate[node] = gpart[tid * 2 + 0] + gpart[tid * 2 + 1] + b2v;
        }
        // next tile's kc loop has syncthreads before gpart is rewritten
    }
}

// Dtype-agnostic batch read. JAX with x64 disabled downcasts int64->int32
// silently; detect at runtime. The batch array is sorted, last value ~8191.
__device__ __forceinline__ int batch_at(const void* batch, int i, int is64) {
    if (is64) return (int)((const long long*)batch)[i];
    return ((const int*)batch)[i];
}

// Segment boundaries from the sorted batch array: g_off[g] = first index with batch >= g
__global__ void offsets_kernel(const void* __restrict__ batch, int N)
{
    int i = blockIdx.x * blockDim.x + threadIdx.x;
    if (i >= N) return;
    const int is64 = (((const int*)batch)[N - 1] == 0) ? 1 : 0;
    int bc = batch_at(batch, i, is64);
    bc = min(max(bc, 0), NGRAPH - 1);
    int bp;
    if (i == 0) bp = -1;
    else {
        bp = batch_at(batch, i - 1, is64);
        bp = min(max(bp, -1), NGRAPH - 1);
    }
    for (int gg = bp + 1; gg <= bc; gg++) g_off[gg] = i;
    if (i == N - 1)
        for (int gg = bc + 1; gg <= NGRAPH; gg++) g_off[gg] = N;
}

// One block per graph: local max -> exp-sum -> weighted feature sum (no atomics)
__global__ __launch_bounds__(256)
void readout_kernel(const float* __restrict__ x, float* __restrict__ out, int N)
{
    const int gid = blockIdx.x;
    const int tid = threadIdx.x;  // column index (H == 256 == blockDim)
    if (N <= 0) { out[(size_t)gid * HID + tid] = 0.f; return; }
    const int s = g_off[gid], e = g_off[gid + 1];
    if (e <= s) { out[(size_t)gid * HID + tid] = 0.f; return; }

    __shared__ float red[256];
    __shared__ float es[CAP];

    // max
    float mx = -3.0e38f;
    for (int i = s + tid; i < e; i += 256) mx = fmaxf(mx, g_gate[i]);
    red[tid] = mx; __syncthreads();
    for (int o = 128; o > 0; o >>= 1) {
        if (tid < o) red[tid] = fmaxf(red[tid], red[tid + o]);
        __syncthreads();
    }
    mx = red[0];
    __syncthreads();

    // sum of exp
    float sm = 0.f;
    for (int i = s + tid; i < e; i += 256) sm += __expf(g_gate[i] - mx);
    red[tid] = sm; __syncthreads();
    for (int o = 128; o > 0; o >>= 1) {
        if (tid < o) red[tid] += red[tid + o];
        __syncthreads();
    }
    const float inv = 1.f / (red[0] + 1e-16f);
    __syncthreads();

    // weighted sum of node features, chunked exp weights in smem
    float a0 = 0.f, a1 = 0.f, a2 = 0.f, a3 = 0.f;
    for (int cs = s; cs < e; cs += CAP) {
        int cn = min(CAP, e - cs);
        for (int i = tid; i < cn; i += 256) es[i] = __expf(g_gate[cs + i] - mx);
        __syncthreads();
        const float* xp = x + (size_t)cs * HID + tid;
        int n = 0;
        for (; n + 4 <= cn; n += 4) {
            a0 += es[n]     * xp[0];
            a1 += es[n + 1] * xp[HID];
            a2 += es[n + 2] * xp[2 * HID];
            a3 += es[n + 3] * xp[3 * HID];
            xp += 4 * HID;
        }
        for (; n < cn; n++) { a0 += es[n] * xp[0]; xp += HID; }
        __syncthreads();
    }
    out[(size_t)gid * HID + tid] = (a0 + a1 + a2 + a3) * inv;
}

extern "C" void kernel_launch(void* const* d_in, const int* in_sizes, int n_in,
                              void* d_out, int out_size)
{
    const float* x     = (const float*)d_in[0];
    const float* W1    = (const float*)d_in[1];
    const float* b1    = (const float*)d_in[2];
    const float* W2    = (const float*)d_in[3];
    const float* b2    = (const float*)d_in[4];
    const void*  batch = d_in[5];
    float* out = (float*)d_out;
    const int N = in_sizes[5];

    (void)n_in; (void)out_size;

    cudaFuncSetAttribute(gate_kernel,
                         cudaFuncAttributeMaxDynamicSharedMemorySize,
                         SMEM_WORDS * 4);

    if (N > 0) {
        int ntiles = (N + 127) / 128;
        int gblocks = ntiles < NSM ? ntiles : NSM;
        offsets_kernel<<<(N + 255) / 256, 256>>>(batch, N);
        gate_kernel<<<gblocks, 256, SMEM_WORDS * 4>>>(x, W1, b1, W2, b2, N, ntiles);
    }
    readout_kernel<<<NGRAPH, 256>>>(x, out, N);
}

// round 8
// speedup vs baseline: 3.6321x; 1.1441x over previous
#include <cuda_runtime.h>
#include <math.h>

#define HID    256
#define HHALF  128
#define NGRAPH 8192
#define NMAX   1048576
#define CAP    1024
#define NSM    148

// Scratch (allocation-free rule: __device__ globals)
__device__ float g_gate[NMAX];
__device__ int   g_off[NGRAPH + 1];

__device__ __forceinline__ unsigned f2tf32(float f) {
    unsigned r;
    asm("cvt.rna.tf32.f32 %0, %1;" : "=r"(r) : "f"(f));
    return r;
}

__device__ __forceinline__ float tanh_fast(float v) {
    float r;
    asm("tanh.approx.f32 %0, %1;" : "=f"(r) : "f"(v));
    return r;
}

__device__ __forceinline__ void mma_tf32(float* d, const unsigned* a, unsigned b0, unsigned b1) {
    asm volatile(
        "mma.sync.aligned.m16n8k8.row.col.f32.tf32.tf32.f32 "
        "{%0,%1,%2,%3}, {%4,%5,%6,%7}, {%8,%9}, {%0,%1,%2,%3};\n"
        : "+f"(d[0]), "+f"(d[1]), "+f"(d[2]), "+f"(d[3])
        : "r"(a[0]), "r"(a[1]), "r"(a[2]), "r"(a[3]), "r"(b0), "r"(b1));
}

// smem word layout (dynamic):
//   W1s : [256][132]  tf32 bits of W1, N-permuted (q=(c&7)*16+(c>>3)) so each
//                     thread's 8 nt-columns are contiguous -> LDS.128 B loads.
//                     stride 132 (mod 32 == 4) -> conflict-free vector phases.
//   xs  : 4 x [128][36] raw fp32 bits of x chunks (cp.async 4-stage ring)
//   b1s : [128], w2s : [128], gpart : [128][2]
#define W1S_STRIDE 132
#define XS_STRIDE  36
#define XS_WORDS   (128 * XS_STRIDE)
#define SMEM_WORDS (HID * W1S_STRIDE + 4 * XS_WORDS + 128 + 128 + 256)

// Stage one 128x32 chunk of x into an xs buffer via cp.async (16B, zero-fill tail)
__device__ __forceinline__ void stage_x(unsigned* xsbuf, const float* __restrict__ x,
                                        int nb, int kc, int N, int tid)
{
    #pragma unroll
    for (int j = 0; j < 4; j++) {
        int idx = tid + j * 256;          // 0..1023
        int r   = idx >> 3;               // row 0..127
        int cw  = (idx & 7) * 4;          // word col 0..28
        int node = nb + r;
        int ok = (node < N);
        const float* src = x + (size_t)(ok ? node : 0) * HID + kc * 32 + cw;
        unsigned daddr = (unsigned)__cvta_generic_to_shared(xsbuf + r * XS_STRIDE + cw);
        int sz = ok ? 16 : 0;
        asm volatile("cp.async.cg.shared.global [%0], [%1], 16, %2;\n"
                     :: "r"(daddr), "l"(src), "r"(sz));
    }
    asm volatile("cp.async.commit_group;\n");
}

__global__ __launch_bounds__(256)
void gate_kernel(const float* __restrict__ x, const float* __restrict__ W1,
                 const float* __restrict__ b1v, const float* __restrict__ W2,
                 const float* __restrict__ b2, int N, int ntiles)
{
    extern __shared__ unsigned smemw[];
    unsigned* W1s   = smemw;                           // 256*132
    unsigned* xsb0  = W1s + HID * W1S_STRIDE;          // 4 x 128*36
    float*    b1s   = (float*)(xsb0 + 4 * XS_WORDS);   // 128
    float*    w2s   = b1s + 128;                       // 128
    float*    gpart = w2s + 128;                       // 128*2

    const int tid  = threadIdx.x;
    const int lane = tid & 31;
    const int warp = tid >> 5;
    const int t    = lane & 3;   // threadID_in_group
    const int g    = lane >> 2;  // groupID
    const int mw   = warp & 3;   // 4 warps along M
    const int nw   = warp >> 2;  // 2 warps along N

    // Stage W1 once per persistent CTA, tf32 bits + N-permutation:
    //   phys q(c) = (c&7)*16 + (c>>3)  (bijective on 0..127)
    for (int idx = tid; idx < HID * HHALF; idx += 256) {
        int k = idx >> 7, c = idx & 127;
        int q = (c & 7) * 16 + (c >> 3);
        W1s[k * W1S_STRIDE + q] = f2tf32(W1[idx]);
    }
    if (tid < 128) { b1s[tid] = b1v[tid]; w2s[tid] = W2[tid]; }
    const float b2v = b2[0];
    __syncthreads();

    // Per-thread base for vectorized B loads: q = g*16 + nw*8 + nt, nt=0..7
    const int bq = g * 16 + nw * 8;

    for (int tile = blockIdx.x; tile < ntiles; tile += gridDim.x) {
        const int nb = tile * 128;

        float acc[2][8][4];
        #pragma unroll
        for (int mt = 0; mt < 2; mt++)
            #pragma unroll
            for (int nt = 0; nt < 8; nt++)
                #pragma unroll
                for (int i = 0; i < 4; i++) acc[mt][nt][i] = 0.f;

        // 4-stage pipeline prologue: chunks 0,1 in flight
        stage_x(xsb0 + 0 * XS_WORDS, x, nb, 0, N, tid);
        stage_x(xsb0 + 1 * XS_WORDS, x, nb, 1, N, tid);

        #pragma unroll
        for (int kc = 0; kc < 8; kc++) {
            if (kc + 2 < 8)
                stage_x(xsb0 + ((kc + 2) & 3) * XS_WORDS, x, nb, kc + 2, N, tid);
            if (kc < 6)      asm volatile("cp.async.wait_group 2;\n");
            else if (kc == 6) asm volatile("cp.async.wait_group 1;\n");
            else              asm volatile("cp.async.wait_group 0;\n");
            __syncthreads();

            const unsigned* xsb = xsb0 + (kc & 3) * XS_WORDS;
            #pragma unroll
            for (int s = 0; s < 4; s++) {
                const int kl = s * 8;
                unsigned a[2][4];
                #pragma unroll
                for (int mt = 0; mt < 2; mt++) {
                    int r0 = mw * 32 + mt * 16 + g;
                    a[mt][0] = xsb[r0 * XS_STRIDE + kl + t];
                    a[mt][1] = xsb[(r0 + 8) * XS_STRIDE + kl + t];
                    a[mt][2] = xsb[r0 * XS_STRIDE + kl + t + 4];
                    a[mt][3] = xsb[(r0 + 8) * XS_STRIDE + kl + t + 4];
                }
                const int kg = kc * 32 + kl;
                // Vector B loads: rows kg+t and kg+t+4, 8 contiguous permuted cols
                const uint4* brow0 = (const uint4*)(W1s + (kg + t) * W1S_STRIDE + bq);
                const uint4* brow1 = (const uint4*)(W1s + (kg + t + 4) * W1S_STRIDE + bq);
                uint4 b0lo = brow0[0], b0hi = brow0[1];
                uint4 b1lo = brow1[0], b1hi = brow1[1];
                unsigned bv0[8] = {b0lo.x, b0lo.y, b0lo.z, b0lo.w, b0hi.x, b0hi.y, b0hi.z, b0hi.w};
                unsigned bv1[8] = {b1lo.x, b1lo.y, b1lo.z, b1lo.w, b1hi.x, b1hi.y, b1hi.z, b1hi.w};
                #pragma unroll
                for (int nt = 0; nt < 8; nt++) {
                    mma_tf32(acc[0][nt], a[0], bv0[nt], bv1[nt]);
                    mma_tf32(acc[1][nt], a[1], bv0[nt], bv1[nt]);
                }
            }
            // single sync per kc: WAR safety comes from staging buffer kc+2
            // (consumed at kc-2; all warps are past sync@kc-1 > compute@kc-2)
        }

        // Epilogue: gate = tanh(pre + b1) . W2 + b2
        #pragma unroll
        for (int mt = 0; mt < 2; mt++) {
            float s0 = 0.f, s1 = 0.f;
            #pragma unroll
            for (int nt = 0; nt < 8; nt++) {
                int c = nw * 64 + nt * 8 + 2 * t;
                float bc0 = b1s[c], bc1 = b1s[c + 1];
                float wc0 = w2s[c], wc1 = w2s[c + 1];
                s0 += tanh_fast(acc[mt][nt][0] + bc0) * wc0 + tanh_fast(acc[mt][nt][1] + bc1) * wc1;
                s1 += tanh_fast(acc[mt][nt][2] + bc0) * wc0 + tanh_fast(acc[mt][nt][3] + bc1) * wc1;
            }
            s0 += __shfl_xor_sync(0xffffffffu, s0, 1);
            s0 += __shfl_xor_sync(0xffffffffu, s0, 2);
            s1 += __shfl_xor_sync(0xffffffffu, s1, 1);
            s1 += __shfl_xor_sync(0xffffffffu, s1, 2);
            if (t == 0) {
                int r = mw * 32 + mt * 16 + g;
                gpart[r * 2 + nw]       = s0;
                gpart[(r + 8) * 2 + nw] = s1;
            }
        }
        __syncthreads();
        if (tid < 128) {
            int node = nb + tid;
            if (node < N)
                g_gate[node] = gpart[tid * 2 + 0] + gpart[tid * 2 + 1] + b2v;
        }
        // gpart rewritten only after 8 syncs of the next tile's kc loop
    }
}

// NOTE on MMA column mapping: the fragment's accumulator column within the
// 8-wide n-tile is 2*t + {0,1}; our permuted B places logical col
// c = nw*64 + nt*8 + g at the mma's n-lane given by... B fragment thread (g,t)
// supplies B rows (k) and the mma's n index comes from the fragment layout:
// for m16n8k8, thread lane = g*4+t holds B[n = g][k = t, t+4] -> our load of
// logical col (nw*64 + nt*8 + g) at thread-group g means acc column n=g maps
// to logical c = nw*64 + nt*8 + g, and accumulator cols 2*t+{0,1} of the
// epilogue below are the D-fragment layout (row-major D: thread (g,t) holds
// D[g][2t], D[g][2t+1], D[g+8][2t], D[g+8][2t+1]) -> epilogue indexing
// c = nw*64 + nt*8 + 2*t matches the previous (passing) kernel unchanged,
// because B's n-lane is determined by which thread supplies the value, and
// the per-thread supplied column differs only by the g<->n association that
// was already in use.

// Dtype-agnostic batch read. JAX with x64 disabled downcasts int64->int32
// silently; detect at runtime. The batch array is sorted, last value ~8191.
__device__ __forceinline__ int batch_at(const void* batch, int i, int is64) {
    if (is64) return (int)((const long long*)batch)[i];
    return ((const int*)batch)[i];
}

// Segment boundaries from the sorted batch array: g_off[g] = first index with batch >= g
__global__ void offsets_kernel(const void* __restrict__ batch, int N)
{
    int i = blockIdx.x * blockDim.x + threadIdx.x;
    if (i >= N) return;
    const int is64 = (((const int*)batch)[N - 1] == 0) ? 1 : 0;
    int bc = batch_at(batch, i, is64);
    bc = min(max(bc, 0), NGRAPH - 1);
    int bp;
    if (i == 0) bp = -1;
    else {
        bp = batch_at(batch, i - 1, is64);
        bp = min(max(bp, -1), NGRAPH - 1);
    }
    for (int gg = bp + 1; gg <= bc; gg++) g_off[gg] = i;
    if (i == N - 1)
        for (int gg = bc + 1; gg <= NGRAPH; gg++) g_off[gg] = N;
}

// One block per graph: local max -> exp-sum -> weighted feature sum (no atomics)
__global__ __launch_bounds__(256)
void readout_kernel(const float* __restrict__ x, float* __restrict__ out, int N)
{
    const int gid = blockIdx.x;
    const int tid = threadIdx.x;  // column index (H == 256 == blockDim)
    if (N <= 0) { out[(size_t)gid * HID + tid] = 0.f; return; }
    const int s = g_off[gid], e = g_off[gid + 1];
    if (e <= s) { out[(size_t)gid * HID + tid] = 0.f; return; }

    __shared__ float red[256];
    __shared__ float es[CAP];

    // max
    float mx = -3.0e38f;
    for (int i = s + tid; i < e; i += 256) mx = fmaxf(mx, g_gate[i]);
    red[tid] = mx; __syncthreads();
    for (int o = 128; o > 0; o >>= 1) {
        if (tid < o) red[tid] = fmaxf(red[tid], red[tid + o]);
        __syncthreads();
    }
    mx = red[0];
    __syncthreads();

    // sum of exp
    float sm = 0.f;
    for (int i = s + tid; i < e; i += 256) sm += __expf(g_gate[i] - mx);
    red[tid] = sm; __syncthreads();
    for (int o = 128; o > 0; o >>= 1) {
        if (tid < o) red[tid] += red[tid + o];
        __syncthreads();
    }
    const float inv = 1.f / (red[0] + 1e-16f);
    __syncthreads();

    // weighted sum of node features, chunked exp weights in smem
    float a0 = 0.f, a1 = 0.f, a2 = 0.f, a3 = 0.f;
    for (int cs = s; cs < e; cs += CAP) {
        int cn = min(CAP, e - cs);
        for (int i = tid; i < cn; i += 256) es[i] = __expf(g_gate[cs + i] - mx);
        __syncthreads();
        const float* xp = x + (size_t)cs * HID + tid;
        int n = 0;
        for (; n + 4 <= cn; n += 4) {
            a0 += es[n]     * xp[0];
            a1 += es[n + 1] * xp[HID];
            a2 += es[n + 2] * xp[2 * HID];
            a3 += es[n + 3] * xp[3 * HID];
            xp += 4 * HID;
        }
        for (; n < cn; n++) { a0 += es[n] * xp[0]; xp += HID; }
        __syncthreads();
    }
    out[(size_t)gid * HID + tid] = (a0 + a1 + a2 + a3) * inv;
}

extern "C" void kernel_launch(void* const* d_in, const int* in_sizes, int n_in,
                              void* d_out, int out_size)
{
    const float* x     = (const float*)d_in[0];
    const float* W1    = (const float*)d_in[1];
    const float* b1    = (const float*)d_in[2];
    const float* W2    = (const float*)d_in[3];
    const float* b2    = (const float*)d_in[4];
    const void*  batch = d_in[5];
    float* out = (float*)d_out;
    const int N = in_sizes[5];

    (void)n_in; (void)out_size;

    cudaFuncSetAttribute(gate_kernel,
                         cudaFuncAttributeMaxDynamicSharedMemorySize,
                         SMEM_WORDS * 4);

    if (N > 0) {
        int ntiles = (N + 127) / 128;
        int gblocks = ntiles < NSM ? ntiles : NSM;
        offsets_kernel<<<(N + 255) / 256, 256>>>(batch, N);
        gate_kernel<<<gblocks, 256, SMEM_WORDS * 4>>>(x, W1, b1, W2, b2, N, ntiles);
    }
    readout_kernel<<<NGRAPH, 256>>>(x, out, N);
}

// round 10
// speedup vs baseline: 4.7238x; 1.3006x over previous
#include <cuda_runtime.h>
#include <cuda_fp16.h>
#include <math.h>

#define HID    256
#define NGRAPH 8192
#define NMAX   1048576
#define CAP    1024
#define NSM    148

// Scratch (allocation-free rule: __device__ globals)
__device__ float g_gate[NMAX];
__device__ int   g_off[NGRAPH + 1];

__device__ __forceinline__ float tanh_fast(float v) {
    float r;
    asm("tanh.approx.f32 %0, %1;" : "=f"(r) : "f"(v));
    return r;
}

// m16n8k16 f16 mma, fp32 accumulate
__device__ __forceinline__ void mma_f16(float* d, const unsigned* a, unsigned b0, unsigned b1) {
    asm volatile(
        "mma.sync.aligned.m16n8k16.row.col.f32.f16.f16.f32 "
        "{%0,%1,%2,%3}, {%4,%5,%6,%7}, {%8,%9}, {%0,%1,%2,%3};\n"
        : "+f"(d[0]), "+f"(d[1]), "+f"(d[2]), "+f"(d[3])
        : "r"(a[0]), "r"(a[1]), "r"(a[2]), "r"(a[3]), "r"(b0), "r"(b1));
}

__device__ __forceinline__ unsigned pack_h2(float lo, float hi) {
    __half2 h = __floats2half2_rn(lo, hi);   // lo -> low 16 bits (smaller k)
    return *(unsigned*)&h;
}

// smem word layout (dynamic):
//   W1p : [128][132]  fp16x2 of W1 packed along k (word k2 = {W1[2k2][c],W1[2k2+1][c]}),
//                     N-permuted (q=(c&7)*16+(c>>3)) -> per-thread LDS.128 B loads.
//                     stride 132: LDS.128 phase banks (33t+4g)%8 all distinct.
//   xs  : 4 x [128][40] raw fp32 of x chunks (cp.async ring); stride 40 ->
//                     LDS.64 A-load phase banks 8g+2t all distinct.
//   b1s : [128], w2s : [128], gpart : [128][2]
#define W1P_STRIDE 132
#define XS_STRIDE  40
#define XS_WORDS   (128 * XS_STRIDE)
#define SMEM_WORDS (128 * W1P_STRIDE + 4 * XS_WORDS + 128 + 128 + 256)

// Stage one 128x32 fp32 chunk of x into an xs buffer via cp.async (16B, zero-fill tail)
__device__ __forceinline__ void stage_x(unsigned* xsbuf, const float* __restrict__ x,
                                        int nb, int kc, int N, int tid)
{
    #pragma unroll
    for (int j = 0; j < 4; j++) {
        int idx = tid + j * 256;          // 0..1023
        int r   = idx >> 3;               // row 0..127
        int cw  = (idx & 7) * 4;          // word col 0..28
        int node = nb + r;
        int ok = (node < N);
        const float* src = x + (size_t)(ok ? node : 0) * HID + kc * 32 + cw;
        unsigned daddr = (unsigned)__cvta_generic_to_shared(xsbuf + r * XS_STRIDE + cw);
        int sz = ok ? 16 : 0;
        asm volatile("cp.async.cg.shared.global [%0], [%1], 16, %2;\n"
                     :: "r"(daddr), "l"(src), "r"(sz));
    }
    asm volatile("cp.async.commit_group;\n");
}

__global__ __launch_bounds__(256)
void gate_kernel(const float* __restrict__ x, const float* __restrict__ W1,
                 const float* __restrict__ b1v, const float* __restrict__ W2,
                 const float* __restrict__ b2, int N, int ntiles)
{
    extern __shared__ unsigned smemw[];
    unsigned* W1p   = smemw;                           // 128*132
    unsigned* xsb0  = W1p + 128 * W1P_STRIDE;          // 4 x 128*40
    float*    b1s   = (float*)(xsb0 + 4 * XS_WORDS);   // 128
    float*    w2s   = b1s + 128;                       // 128
    float*    gpart = w2s + 128;                       // 128*2

    const int tid  = threadIdx.x;
    const int lane = tid & 31;
    const int warp = tid >> 5;
    const int t    = lane & 3;   // threadID_in_group
    const int g    = lane >> 2;  // groupID
    const int mw   = warp & 3;   // 4 warps along M
    const int nw   = warp >> 2;  // 2 warps along N

    // Stage W1 once per persistent CTA: fp16x2 k-packed + N-permutation
    //   phys q(c) = (c&7)*16 + (c>>3)  (bijective on 0..127)
    for (int idx = tid; idx < 128 * 128; idx += 256) {
        int k2 = idx >> 7, c = idx & 127;              // k2 = k/2
        int q = (c & 7) * 16 + (c >> 3);
        W1p[k2 * W1P_STRIDE + q] =
            pack_h2(W1[(2 * k2) * 128 + c], W1[(2 * k2 + 1) * 128 + c]);
    }
    if (tid < 128) { b1s[tid] = b1v[tid]; w2s[tid] = W2[tid]; }
    const float b2v = b2[0];
    __syncthreads();

    // Per-thread base for vectorized B loads: q = g*16 + nw*8 + nt, nt=0..7
    const int bq = g * 16 + nw * 8;

    for (int tile = blockIdx.x; tile < ntiles; tile += gridDim.x) {
        const int nb = tile * 128;

        float acc[2][8][4];
        #pragma unroll
        for (int mt = 0; mt < 2; mt++)
            #pragma unroll
            for (int nt = 0; nt < 8; nt++)
                #pragma unroll
                for (int i = 0; i < 4; i++) acc[mt][nt][i] = 0.f;

        // 4-stage pipeline prologue: chunks 0,1 in flight
        stage_x(xsb0 + 0 * XS_WORDS, x, nb, 0, N, tid);
        stage_x(xsb0 + 1 * XS_WORDS, x, nb, 1, N, tid);

        #pragma unroll
        for (int kc = 0; kc < 8; kc++) {
            if (kc + 2 < 8)
                stage_x(xsb0 + ((kc + 2) & 3) * XS_WORDS, x, nb, kc + 2, N, tid);
            if (kc < 6)       asm volatile("cp.async.wait_group 2;\n");
            else if (kc == 6) asm volatile("cp.async.wait_group 1;\n");
            else              asm volatile("cp.async.wait_group 0;\n");
            __syncthreads();

            const float* xsb = (const float*)(xsb0 + (kc & 3) * XS_WORDS);
            #pragma unroll
            for (int s = 0; s < 2; s++) {
                const int kl = s * 16;
                // A fragments: m16n8k16 -> consecutive-k fp32 pairs, cvt to f16x2
                unsigned a[2][4];
                #pragma unroll
                for (int mt = 0; mt < 2; mt++) {
                    int r0 = mw * 32 + mt * 16 + g;
                    float2 v0 = *(const float2*)(xsb + r0 * XS_STRIDE + kl + 2 * t);
                    float2 v1 = *(const float2*)(xsb + (r0 + 8) * XS_STRIDE + kl + 2 * t);
                    float2 v2 = *(const float2*)(xsb + r0 * XS_STRIDE + kl + 2 * t + 8);
                    float2 v3 = *(const float2*)(xsb + (r0 + 8) * XS_STRIDE + kl + 2 * t + 8);
                    a[mt][0] = pack_h2(v0.x, v0.y);
                    a[mt][1] = pack_h2(v1.x, v1.y);
                    a[mt][2] = pack_h2(v2.x, v2.y);
                    a[mt][3] = pack_h2(v3.x, v3.y);
                }
                // B fragments: rows k2 = kc*16 + s*8 + t and +4, 8 permuted cols
                const int k2 = kc * 16 + s * 8;
                const uint4* p0 = (const uint4*)(W1p + (k2 + t) * W1P_STRIDE + bq);
                const uint4* p1 = (const uint4*)(W1p + (k2 + t + 4) * W1P_STRIDE + bq);
                uint4 b0lo = p0[0], b0hi = p0[1];
                uint4 b1lo = p1[0], b1hi = p1[1];
                unsigned bv0[8] = {b0lo.x, b0lo.y, b0lo.z, b0lo.w, b0hi.x, b0hi.y, b0hi.z, b0hi.w};
                unsigned bv1[8] = {b1lo.x, b1lo.y, b1lo.z, b1lo.w, b1hi.x, b1hi.y, b1hi.z, b1hi.w};
                #pragma unroll
                for (int nt = 0; nt < 8; nt++) {
                    mma_f16(acc[0][nt], a[0], bv0[nt], bv1[nt]);
                    mma_f16(acc[1][nt], a[1], bv0[nt], bv1[nt]);
                }
            }
            // single sync per kc: WAR safety from staging buffer kc+2
            // (consumed at kc-2; all warps are past sync@kc-1 > compute@kc-2)
        }

        // Epilogue: gate = tanh(pre + b1) . W2 + b2
        // D fragment of m16n8k16 == m16n8k8: thread (g,t) holds
        // D[g][2t], D[g][2t+1], D[g+8][2t], D[g+8][2t+1]; logical col = nw*64+nt*8+n
        #pragma unroll
        for (int mt = 0; mt < 2; mt++) {
            float s0 = 0.f, s1 = 0.f;
            #pragma unroll
            for (int nt = 0; nt < 8; nt++) {
                int c = nw * 64 + nt * 8 + 2 * t;
                float bc0 = b1s[c], bc1 = b1s[c + 1];
                float wc0 = w2s[c], wc1 = w2s[c + 1];
                s0 += tanh_fast(acc[mt][nt][0] + bc0) * wc0 + tanh_fast(acc[mt][nt][1] + bc1) * wc1;
                s1 += tanh_fast(acc[mt][nt][2] + bc0) * wc0 + tanh_fast(acc[mt][nt][3] + bc1) * wc1;
            }
            s0 += __shfl_xor_sync(0xffffffffu, s0, 1);
            s0 += __shfl_xor_sync(0xffffffffu, s0, 2);
            s1 += __shfl_xor_sync(0xffffffffu, s1, 1);
            s1 += __shfl_xor_sync(0xffffffffu, s1, 2);
            if (t == 0) {
                int r = mw * 32 + mt * 16 + g;
                gpart[r * 2 + nw]       = s0;
                gpart[(r + 8) * 2 + nw] = s1;
            }
        }
        __syncthreads();
        if (tid < 128) {
            int node = nb + tid;
            if (node < N)
                g_gate[node] = gpart[tid * 2 + 0] + gpart[tid * 2 + 1] + b2v;
        }
        // gpart rewritten only after 8 syncs of the next tile's kc loop
    }
}

// Dtype-agnostic batch read. JAX with x64 disabled downcasts int64->int32
// silently; detect at runtime. The batch array is sorted, last value ~8191.
__device__ __forceinline__ int batch_at(const void* batch, int i, int is64) {
    if (is64) return (int)((const long long*)batch)[i];
    return ((const int*)batch)[i];
}

// Segment boundaries from the sorted batch array: g_off[g] = first index with batch >= g
__global__ void offsets_kernel(const void* __restrict__ batch, int N)
{
    int i = blockIdx.x * blockDim.x + threadIdx.x;
    if (i >= N) return;
    const int is64 = (((const int*)batch)[N - 1] == 0) ? 1 : 0;
    int bc = batch_at(batch, i, is64);
    bc = min(max(bc, 0), NGRAPH - 1);
    int bp;
    if (i == 0) bp = -1;
    else {
        bp = batch_at(batch, i - 1, is64);
        bp = min(max(bp, -1), NGRAPH - 1);
    }
    for (int gg = bp + 1; gg <= bc; gg++) g_off[gg] = i;
    if (i == N - 1)
        for (int gg = bc + 1; gg <= NGRAPH; gg++) g_off[gg] = N;
}

// One block per graph: local max -> exp-sum -> weighted feature sum (no atomics)
__global__ __launch_bounds__(256)
void readout_kernel(const float* __restrict__ x, float* __restrict__ out, int N)
{
    const int gid = blockIdx.x;
    const int tid = threadIdx.x;  // column index (H == 256 == blockDim)
    if (N <= 0) { out[(size_t)gid * HID + tid] = 0.f; return; }
    const int s = g_off[gid], e = g_off[gid + 1];
    if (e <= s) { out[(size_t)gid * HID + tid] = 0.f; return; }

    __shared__ float red[256];
    __shared__ float es[CAP];

    // max
    float mx = -3.0e38f;
    for (int i = s + tid; i < e; i += 256) mx = fmaxf(mx, g_gate[i]);
    red[tid] = mx; __syncthreads();
    for (int o = 128; o > 0; o >>= 1) {
        if (tid < o) red[tid] = fmaxf(red[tid], red[tid + o]);
        __syncthreads();
    }
    mx = red[0];
    __syncthreads();

    // sum of exp
    float sm = 0.f;
    for (int i = s + tid; i < e; i += 256) sm += __expf(g_gate[i] - mx);
    red[tid] = sm; __syncthreads();
    for (int o = 128; o > 0; o >>= 1) {
        if (tid < o) red[tid] += red[tid + o];
        __syncthreads();
    }
    const float inv = 1.f / (red[0] + 1e-16f);
    __syncthreads();

    // weighted sum of node features, chunked exp weights in smem
    float a0 = 0.f, a1 = 0.f, a2 = 0.f, a3 = 0.f;
    for (int cs = s; cs < e; cs += CAP) {
        int cn = min(CAP, e - cs);
        for (int i = tid; i < cn; i += 256) es[i] = __expf(g_gate[cs + i] - mx);
        __syncthreads();
        const float* xp = x + (size_t)cs * HID + tid;
        int n = 0;
        for (; n + 4 <= cn; n += 4) {
            a0 += es[n]     * xp[0];
            a1 += es[n + 1] * xp[HID];
            a2 += es[n + 2] * xp[2 * HID];
            a3 += es[n + 3] * xp[3 * HID];
            xp += 4 * HID;
        }
        for (; n < cn; n++) { a0 += es[n] * xp[0]; xp += HID; }
        __syncthreads();
    }
    out[(size_t)gid * HID + tid] = (a0 + a1 + a2 + a3) * inv;
}

extern "C" void kernel_launch(void* const* d_in, const int* in_sizes, int n_in,
                              void* d_out, int out_size)
{
    const float* x     = (const float*)d_in[0];
    const float* W1    = (const float*)d_in[1];
    const float* b1    = (const float*)d_in[2];
    const float* W2    = (const float*)d_in[3];
    const float* b2    = (const float*)d_in[4];
    const void*  batch = d_in[5];
    float* out = (float*)d_out;
    const int N = in_sizes[5];

    (void)n_in; (void)out_size;

    cudaFuncSetAttribute(gate_kernel,
                         cudaFuncAttributeMaxDynamicSharedMemorySize,
                         SMEM_WORDS * 4);

    if (N > 0) {
        int ntiles = (N + 127) / 128;
        int gblocks = ntiles < NSM ? ntiles : NSM;
        offsets_kernel<<<(N + 255) / 256, 256>>>(batch, N);
        gate_kernel<<<gblocks, 256, SMEM_WORDS * 4>>>(x, W1, b1, W2, b2, N, ntiles);
    }
    readout_kernel<<<NGRAPH, 256>>>(x, out, N);
}